// round 11
// baseline (speedup 1.0000x reference)
#include <cuda_runtime.h>
#include <cuda_bf16.h>
#include <math.h>
#include <stdint.h>

#define NU 40000
#define NI 20000
#define NT 60000
#define DD 256
#define NNZ_ADJ 960000
#define NNZ_UP  640000
#define NNZ_IP  320000
#define NNZ_ALL (NNZ_ADJ + NNZ_UP + NNZ_IP)
#define NROWS_ALL (NT + NU + NI)            /* 120000 */
#define SCAN_NB ((NROWS_ALL + 1023) / 1024) /* 118 */

#define NRB_U ((NU + 127) / 128)  /* 313 */
#define NRB_I ((NI + 127) / 128)  /* 157 */
#define NRB (NRB_U + NRB_I)       /* 470 */

typedef __nv_bfloat16 bf16;

// ======================= device scratch =====================================
__device__ bf16 g_pre0h[(size_t)NT * DD], g_pre0l[(size_t)NT * DD];
__device__ bf16 g_aggh[(size_t)NT * DD],  g_aggl[(size_t)NT * DD];
__device__ bf16 g_pairh[(size_t)NT * DD], g_pairl[(size_t)NT * DD];
__device__ bf16 g_embh[(size_t)NT * DD],  g_embl[(size_t)NT * DD];
__device__ float g_h[(size_t)NT * DD];   // hpart, then final h (in place)
__device__ float g_norm[NT];
// transposed + split weights ([0]=user, [1]=item)
__device__ bf16 g_Qth[2][DD * DD],     g_Qtl[2][DD * DD];
__device__ bf16 g_Wth[2][DD * 2 * DD], g_Wtl[2][DD * 2 * DD];
__device__ bf16 g_Mth[2][DD * DD],     g_Mtl[2][DD * DD];
// CSR build
__device__ int   g_cnt[NROWS_ALL];
__device__ int   g_rs[NROWS_ALL + 1];
__device__ int   g_cur[NROWS_ALL];
__device__ int2  g_cpack[NNZ_ALL];
__device__ int   g_bsum[SCAN_NB], g_boff[SCAN_NB + 1];

__device__ __forceinline__ void bsplit(float x, bf16& h, bf16& l) {
    h = __float2bfloat16_rn(x);
    l = __float2bfloat16_rn(x - __bfloat162float(h));
}
__device__ __forceinline__ uint32_t smem_u32(const void* p) {
    uint32_t a;
    asm("{ .reg .u64 t; cvta.to.shared.u64 t, %1; cvt.u32.u64 %0, t; }" : "=r"(a) : "l"(p));
    return a;
}

// ======================= CSR build ==========================================
__global__ void k_zero_cnt() {
    int i = blockIdx.x * blockDim.x + threadIdx.x;
    if (i < NROWS_ALL) g_cnt[i] = 0;
    if (i < NT) g_norm[i] = 0.f;
}
__global__ void k_hist_all(const int* __restrict__ ra, const int* __restrict__ ru,
                           const int* __restrict__ ri) {
    int i = blockIdx.x * blockDim.x + threadIdx.x;
    if (i < NNZ_ADJ)                 atomicAdd(&g_cnt[ra[i]], 1);
    else if (i < NNZ_ADJ + NNZ_UP)   atomicAdd(&g_cnt[ru[i - NNZ_ADJ] + NT], 1);
    else if (i < NNZ_ALL)            atomicAdd(&g_cnt[ri[i - NNZ_ADJ - NNZ_UP] + NT + NU], 1);
}
__global__ __launch_bounds__(1024) void k_scan_blk() {
    __shared__ int s[1024];
    int i = blockIdx.x * 1024 + threadIdx.x;
    int v = (i < NROWS_ALL) ? g_cnt[i] : 0;
    s[threadIdx.x] = v;
    __syncthreads();
    int x = v;
    for (int off = 1; off < 1024; off <<= 1) {
        int t = (threadIdx.x >= off) ? s[threadIdx.x - off] : 0;
        __syncthreads();
        x += t;
        s[threadIdx.x] = x;
        __syncthreads();
    }
    if (i < NROWS_ALL) g_rs[i] = x - v;
    if (threadIdx.x == 1023) g_bsum[blockIdx.x] = s[1023];
}
__global__ void k_scan_top() {
    if (threadIdx.x == 0) {
        int run = 0;
        for (int b = 0; b < SCAN_NB; b++) { g_boff[b] = run; run += g_bsum[b]; }
        g_boff[SCAN_NB] = run;
    }
}
__global__ void k_scan_add() {
    int i = blockIdx.x * 1024 + threadIdx.x;
    if (i < NROWS_ALL) {
        int r = g_rs[i] + g_boff[i >> 10];
        g_rs[i] = r;
        g_cur[i] = r;
    }
    if (i == 0) g_rs[NROWS_ALL] = g_boff[SCAN_NB];
}
__global__ void k_scatter_all(
    const int* __restrict__ ra, const int* __restrict__ ca, const float* __restrict__ va,
    const int* __restrict__ ru, const int* __restrict__ cu, const float* __restrict__ vu,
    const int* __restrict__ ri, const int* __restrict__ ci, const float* __restrict__ vi) {
    int i = blockIdx.x * blockDim.x + threadIdx.x;
    int r, c; float v;
    if (i < NNZ_ADJ)               { r = ra[i];                     c = ca[i];                     v = va[i]; }
    else if (i < NNZ_ADJ + NNZ_UP) { int j = i - NNZ_ADJ;           r = ru[j] + NT;                c = cu[j]; v = vu[j]; }
    else if (i < NNZ_ALL)          { int j = i - NNZ_ADJ - NNZ_UP;  r = ri[j] + NT + NU;           c = ci[j]; v = vi[j]; }
    else return;
    int p = atomicAdd(&g_cur[r], 1);
    g_cpack[p] = make_int2(c, __float_as_int(v));
}

// ======================= CSR SpMM (warp/row, x4 unroll, row range) ==========
__global__ __launch_bounds__(256) void k_spmm(const float* __restrict__ Ue,
                                              const float* __restrict__ Ie,
                                              int r0, int r1) {
    int R = r0 + blockIdx.x * 8 + (threadIdx.x >> 5);
    if (R >= r1) return;
    int lane = threadIdx.x & 31;
    const float* X1;
    const float* X2;
    int split;
    bf16 *oh, *ol;
    int orow;
    if (R < NT)            { X1 = Ue; X2 = Ie; split = NU;      oh = g_aggh;  ol = g_aggl;  orow = R; }
    else if (R < NT + NU)  { X1 = Ue; X2 = Ue; split = 1 << 30; oh = g_pairh; ol = g_pairl; orow = R - NT; }
    else                   { X1 = Ie; X2 = Ie; split = 1 << 30; oh = g_pairh; ol = g_pairl; orow = R - NT; }

    float4 a0 = make_float4(0.f, 0.f, 0.f, 0.f);
    float4 a1 = a0;
    int beg = g_rs[R], end = g_rs[R + 1];
    int e = beg;
    for (; e + 3 < end; e += 4) {
        int2 cv[4];
        const float* xp[4];
        float v[4];
#pragma unroll
        for (int j = 0; j < 4; j++) {
            cv[j] = g_cpack[e + j];
            v[j] = __int_as_float(cv[j].y);
            xp[j] = (cv[j].x < split) ? (X1 + (size_t)cv[j].x * DD)
                                      : (X2 + (size_t)(cv[j].x - split) * DD);
        }
        float4 p[4], q[4];
#pragma unroll
        for (int j = 0; j < 4; j++) {
            p[j] = *reinterpret_cast<const float4*>(xp[j] + lane * 4);
            q[j] = *reinterpret_cast<const float4*>(xp[j] + 128 + lane * 4);
        }
#pragma unroll
        for (int j = 0; j < 4; j++) {
            a0.x += v[j] * p[j].x; a0.y += v[j] * p[j].y;
            a0.z += v[j] * p[j].z; a0.w += v[j] * p[j].w;
            a1.x += v[j] * q[j].x; a1.y += v[j] * q[j].y;
            a1.z += v[j] * q[j].z; a1.w += v[j] * q[j].w;
        }
    }
    for (; e < end; e++) {
        int2 cv = g_cpack[e];
        float v = __int_as_float(cv.y);
        const float* x = (cv.x < split) ? (X1 + (size_t)cv.x * DD) : (X2 + (size_t)(cv.x - split) * DD);
        float4 p0 = *reinterpret_cast<const float4*>(x + lane * 4);
        float4 p1 = *reinterpret_cast<const float4*>(x + 128 + lane * 4);
        a0.x += v * p0.x; a0.y += v * p0.y; a0.z += v * p0.z; a0.w += v * p0.w;
        a1.x += v * p1.x; a1.y += v * p1.y; a1.z += v * p1.z; a1.w += v * p1.w;
    }
    size_t base = (size_t)orow * DD + lane * 4;
    bf16 h0, l0, h1, l1, h2, l2, h3, l3;
    bsplit(a0.x, h0, l0); bsplit(a0.y, h1, l1); bsplit(a0.z, h2, l2); bsplit(a0.w, h3, l3);
    oh[base + 0] = h0; oh[base + 1] = h1; oh[base + 2] = h2; oh[base + 3] = h3;
    ol[base + 0] = l0; ol[base + 1] = l1; ol[base + 2] = l2; ol[base + 3] = l3;
    bsplit(a1.x, h0, l0); bsplit(a1.y, h1, l1); bsplit(a1.z, h2, l2); bsplit(a1.w, h3, l3);
    oh[base + 128] = h0; oh[base + 129] = h1; oh[base + 130] = h2; oh[base + 131] = h3;
    ol[base + 128] = l0; ol[base + 129] = l1; ol[base + 130] = l2; ol[base + 131] = l3;
}

// ======================= conversions =========================================
__global__ void k_conv_pre0(const float* __restrict__ Ue, const float* __restrict__ Ie) {
    size_t i = (size_t)blockIdx.x * blockDim.x + threadIdx.x;
    if (i >= (size_t)NT * DD / 4) return;
    size_t base = i * 4;
    const float* src = (base < (size_t)NU * DD) ? (Ue + base) : (Ie + base - (size_t)NU * DD);
    float4 v = *reinterpret_cast<const float4*>(src);
    bf16 h, l;
    bsplit(v.x, h, l); g_pre0h[base + 0] = h; g_pre0l[base + 0] = l;
    bsplit(v.y, h, l); g_pre0h[base + 1] = h; g_pre0l[base + 1] = l;
    bsplit(v.z, h, l); g_pre0h[base + 2] = h; g_pre0l[base + 2] = l;
    bsplit(v.w, h, l); g_pre0h[base + 3] = h; g_pre0l[base + 3] = l;
}

// all 6 weight matrices: transpose + split in one launch
#define TS_SMALL (4 * DD * DD)            /* Qu Qi Mu Mi */
#define TS_TOTAL (TS_SMALL + 2 * 2 * DD * DD)
__global__ void k_tsplit_all(
    const float* __restrict__ Qu, const float* __restrict__ Qi,
    const float* __restrict__ Mu, const float* __restrict__ Mi,
    const float* __restrict__ Wu, const float* __restrict__ Wi) {
    int i = blockIdx.x * blockDim.x + threadIdx.x;
    if (i >= TS_TOTAL) return;
    const float* W;
    bf16 *Th, *Tl;
    int K, j;
    if (i < TS_SMALL) {
        int seg = i >> 16; j = i & 65535; K = DD;
        if (seg == 0)      { W = Qu; Th = g_Qth[0]; Tl = g_Qtl[0]; }
        else if (seg == 1) { W = Qi; Th = g_Qth[1]; Tl = g_Qtl[1]; }
        else if (seg == 2) { W = Mu; Th = g_Mth[0]; Tl = g_Mtl[0]; }
        else               { W = Mi; Th = g_Mth[1]; Tl = g_Mtl[1]; }
    } else {
        j = i - TS_SMALL; K = 2 * DD;
        if (j < 2 * DD * DD) { W = Wu; Th = g_Wth[0]; Tl = g_Wtl[0]; }
        else { j -= 2 * DD * DD; W = Wi; Th = g_Wth[1]; Tl = g_Wtl[1]; }
    }
    int k = j >> 8, n = j & 255;
    bf16 h, l;
    bsplit(W[j], h, l);
    Th[(size_t)n * K + k] = h;
    Tl[(size_t)n * K + k] = l;
}

// ======================= legacy-HMMA bf16 GEMM ==============================
__device__ __forceinline__ void mma_bf16(float c[4], const uint32_t a[4],
                                         uint32_t b0, uint32_t b1) {
    asm volatile(
        "mma.sync.aligned.m16n8k16.row.col.f32.bf16.bf16.f32 "
        "{%0,%1,%2,%3}, {%4,%5,%6,%7}, {%8,%9}, {%0,%1,%2,%3};"
        : "+f"(c[0]), "+f"(c[1]), "+f"(c[2]), "+f"(c[3])
        : "r"(a[0]), "r"(a[1]), "r"(a[2]), "r"(a[3]), "r"(b0), "r"(b1));
}

#define SPAD 40
#define SARR (128 * SPAD)
#define STAGE_ELEMS (4 * SARR)
#define STAGE_BYTES (STAGE_ELEMS * 2)     /* 40960 */
#define GSM_TOTAL   (2 * STAGE_BYTES)     /* 81920 -> 2 CTAs/SM */

__device__ __forceinline__ void cpa16(uint32_t dst, const void* src, bool pred) {
    uint32_t sz = pred ? 16u : 0u;
    asm volatile("cp.async.cg.shared.global [%0], [%1], 16, %2;"
                 :: "r"(dst), "l"(src), "r"(sz));
}
#define CP_COMMIT() asm volatile("cp.async.commit_group;" ::: "memory")

__device__ __forceinline__ uint32_t ld32s(const bf16* s, int elem) {
    return *reinterpret_cast<const uint32_t*>(s + elem);
}

// CTA: 128(m) x 128(n), 8 warps (4m x 2n), warp tile 32x64, K-chunks of 32,
// cp.async double-buffered, 2 CTAs/SM.
// modes: 0 emb=tanh(A@B)->Oh/Ol
//        1 h=tanh(A@B + Hin + bias)->Og (in place ok), +g_norm
//        2 out=Hin*rsnorm + tanh(A@B)->Og
//        3 hpart=A@B (raw fp32)->Og
__global__ __launch_bounds__(256, 2) void k_gemm(
    int mode, int nch, int nsplit,
    const bf16* __restrict__ A1h, const bf16* __restrict__ A1l,
    const bf16* __restrict__ A2h, const bf16* __restrict__ A2l,
    const bf16* __restrict__ Bth_u, const bf16* __restrict__ Btl_u,
    const bf16* __restrict__ Bth_i, const bf16* __restrict__ Btl_i, int ldb,
    const float* __restrict__ bias_u, const float* __restrict__ bias_i,
    bf16* __restrict__ Oh, bf16* __restrict__ Ol,
    float* __restrict__ Og, const float* __restrict__ Hin)
{
    extern __shared__ char smem[];
    const uint32_t sbase = smem_u32(smem);

    const int tid = threadIdx.x;
    const int wid = tid >> 5, lane = tid & 31;
    const int wm = wid & 3, wn = wid >> 2;
    const int g = lane >> 2, tg = lane & 3;
    const int b = blockIdx.x;
    const bool user = (b < NRB_U);
    const int row0 = user ? b * 128 : NU + (b - NRB_U) * 128;
    const int row_end = user ? NU : NT;
    const int valid = min(128, row_end - row0);
    const int n0 = blockIdx.y * 128;
    const bf16* __restrict__ Bh = user ? Bth_u : Bth_i;
    const bf16* __restrict__ Bl = user ? Btl_u : Btl_i;
    const float* __restrict__ bias = user ? bias_u : bias_i;

    const int la_r = tid >> 1;
    const int la_kq = (tid & 1) * 2;

    float acc[2][8][4];
#pragma unroll
    for (int mi = 0; mi < 2; mi++)
#pragma unroll
        for (int ni = 0; ni < 8; ni++)
#pragma unroll
            for (int j = 0; j < 4; j++) acc[mi][ni][j] = 0.f;

    auto load_stage = [&](int s, int ch) {
        const bf16* Ah = (ch < nsplit) ? A1h : A2h;
        const bf16* Al = (ch < nsplit) ? A1l : A2l;
        const int ka = ((ch < nsplit) ? ch : ch - nsplit) * 32;
        const int kb = ch * 32;
        const uint32_t st = sbase + s * STAGE_BYTES;
        const uint32_t oAh = st;
        const uint32_t oAl = st + SARR * 2;
        const uint32_t oBh = st + 2 * SARR * 2;
        const uint32_t oBl = st + 3 * SARR * 2;
        bool pa = la_r < valid;
        size_t ga = (size_t)(row0 + (pa ? la_r : 0)) * DD + ka + la_kq * 8;
        size_t gb = (size_t)(n0 + la_r) * ldb + kb + la_kq * 8;
        uint32_t so = (la_r * SPAD + la_kq * 8) * 2;
#pragma unroll
        for (int q = 0; q < 2; q++) {
            uint32_t soq = so + q * 16;
            size_t gaq = ga + q * 8;
            size_t gbq = gb + q * 8;
            cpa16(oAh + soq, Ah + gaq, pa);
            cpa16(oAl + soq, Al + gaq, pa);
            cpa16(oBh + soq, Bh + gbq, true);
            cpa16(oBl + soq, Bl + gbq, true);
        }
        CP_COMMIT();
    };

    load_stage(0, 0);

    for (int ch = 0; ch < nch; ch++) {
        if (ch + 1 < nch) {
            load_stage((ch + 1) & 1, ch + 1);
            asm volatile("cp.async.wait_group 1;" ::: "memory");
        } else {
            asm volatile("cp.async.wait_group 0;" ::: "memory");
        }
        __syncthreads();

        const bf16* st = reinterpret_cast<const bf16*>(smem + (ch & 1) * STAGE_BYTES);
        const bf16* sAh = st;
        const bf16* sAl = st + SARR;
        const bf16* sBh = st + 2 * SARR;
        const bf16* sBl = st + 3 * SARR;

#pragma unroll
        for (int ks = 0; ks < 2; ks++) {
            const int kc = ks * 16 + 2 * tg;
            uint32_t ah[2][4], al[2][4];
#pragma unroll
            for (int mi = 0; mi < 2; mi++) {
                int rb = (wm * 32 + mi * 16 + g) * SPAD;
                ah[mi][0] = ld32s(sAh, rb + kc);
                ah[mi][1] = ld32s(sAh, rb + 8 * SPAD + kc);
                ah[mi][2] = ld32s(sAh, rb + kc + 8);
                ah[mi][3] = ld32s(sAh, rb + 8 * SPAD + kc + 8);
                al[mi][0] = ld32s(sAl, rb + kc);
                al[mi][1] = ld32s(sAl, rb + 8 * SPAD + kc);
                al[mi][2] = ld32s(sAl, rb + kc + 8);
                al[mi][3] = ld32s(sAl, rb + 8 * SPAD + kc + 8);
            }
#pragma unroll
            for (int ni = 0; ni < 8; ni++) {
                int nb = (wn * 64 + ni * 8 + g) * SPAD;
                uint32_t bh0 = ld32s(sBh, nb + kc);
                uint32_t bh1 = ld32s(sBh, nb + kc + 8);
                uint32_t bl0 = ld32s(sBl, nb + kc);
                uint32_t bl1 = ld32s(sBl, nb + kc + 8);
#pragma unroll
                for (int mi = 0; mi < 2; mi++) {
                    mma_bf16(acc[mi][ni], ah[mi], bh0, bh1);
                    mma_bf16(acc[mi][ni], ah[mi], bl0, bl1);
                    mma_bf16(acc[mi][ni], al[mi], bh0, bh1);
                }
            }
        }
        __syncthreads();
    }

    // ---------------- epilogue ----------------
    const int mbase = row0 + wm * 32 + g;
    float scl[2][2];
    if (mode == 2) {
#pragma unroll
        for (int mi = 0; mi < 2; mi++) {
            int r0 = mbase + mi * 16, r1 = r0 + 8;
            scl[mi][0] = (r0 < row_end) ? 1.f / fmaxf(sqrtf(g_norm[r0]), 1e-12f) : 0.f;
            scl[mi][1] = (r1 < row_end) ? 1.f / fmaxf(sqrtf(g_norm[r1]), 1e-12f) : 0.f;
        }
    }
    float ssum[4] = {0.f, 0.f, 0.f, 0.f};

#pragma unroll
    for (int mi = 0; mi < 2; mi++) {
        int r0 = mbase + mi * 16, r1 = r0 + 8;
        bool v0 = (r0 < row_end), v1 = (r1 < row_end);
#pragma unroll
        for (int ni = 0; ni < 8; ni++) {
            int col = n0 + wn * 64 + ni * 8 + 2 * tg;
            float* a = acc[mi][ni];
            if (mode == 0) {
                if (v0) {
                    float t0 = tanhf(a[0]), t1 = tanhf(a[1]);
                    bf16 h0, l0, h1, l1;
                    bsplit(t0, h0, l0); bsplit(t1, h1, l1);
                    size_t idx = (size_t)r0 * DD + col;
                    *reinterpret_cast<__nv_bfloat162*>(Oh + idx) = __nv_bfloat162(h0, h1);
                    *reinterpret_cast<__nv_bfloat162*>(Ol + idx) = __nv_bfloat162(l0, l1);
                }
                if (v1) {
                    float t2 = tanhf(a[2]), t3 = tanhf(a[3]);
                    bf16 h2, l2, h3, l3;
                    bsplit(t2, h2, l2); bsplit(t3, h3, l3);
                    size_t idx = (size_t)r1 * DD + col;
                    *reinterpret_cast<__nv_bfloat162*>(Oh + idx) = __nv_bfloat162(h2, h3);
                    *reinterpret_cast<__nv_bfloat162*>(Ol + idx) = __nv_bfloat162(l2, l3);
                }
            } else if (mode == 1) {
                float b0v = bias[col], b1v = bias[col + 1];
                if (v0) {
                    size_t idx = (size_t)r0 * DD + col;
                    float t0 = tanhf(a[0] + Hin[idx] + b0v);
                    float t1 = tanhf(a[1] + Hin[idx + 1] + b1v);
                    Og[idx] = t0; Og[idx + 1] = t1;
                    ssum[mi * 2] += t0 * t0 + t1 * t1;
                }
                if (v1) {
                    size_t idx = (size_t)r1 * DD + col;
                    float t2 = tanhf(a[2] + Hin[idx] + b0v);
                    float t3 = tanhf(a[3] + Hin[idx + 1] + b1v);
                    Og[idx] = t2; Og[idx + 1] = t3;
                    ssum[mi * 2 + 1] += t2 * t2 + t3 * t3;
                }
            } else if (mode == 2) {
                if (v0) {
                    size_t idx = (size_t)r0 * DD + col;
                    Og[idx]     = Hin[idx]     * scl[mi][0] + tanhf(a[0]);
                    Og[idx + 1] = Hin[idx + 1] * scl[mi][0] + tanhf(a[1]);
                }
                if (v1) {
                    size_t idx = (size_t)r1 * DD + col;
                    Og[idx]     = Hin[idx]     * scl[mi][1] + tanhf(a[2]);
                    Og[idx + 1] = Hin[idx + 1] * scl[mi][1] + tanhf(a[3]);
                }
            } else {  // mode 3: raw fp32 partial
                if (v0) {
                    size_t idx = (size_t)r0 * DD + col;
                    Og[idx] = a[0]; Og[idx + 1] = a[1];
                }
                if (v1) {
                    size_t idx = (size_t)r1 * DD + col;
                    Og[idx] = a[2]; Og[idx + 1] = a[3];
                }
            }
        }
    }
    if (mode == 1) {
#pragma unroll
        for (int j = 0; j < 4; j++) {
            ssum[j] += __shfl_xor_sync(0xFFFFFFFF, ssum[j], 1);
            ssum[j] += __shfl_xor_sync(0xFFFFFFFF, ssum[j], 2);
        }
        if (tg == 0) {
#pragma unroll
            for (int mi = 0; mi < 2; mi++) {
                int r0 = mbase + mi * 16, r1 = r0 + 8;
                if (r0 < row_end) atomicAdd(&g_norm[r0], ssum[mi * 2]);
                if (r1 < row_end) atomicAdd(&g_norm[r1], ssum[mi * 2 + 1]);
            }
        }
    }
}

// ======================= host ================================================
extern "C" void kernel_launch(void* const* d_in, const int* in_sizes, int n_in,
                              void* d_out, int out_size) {
    const int*   adj_rows = (const int*)d_in[0];
    const int*   adj_cols = (const int*)d_in[1];
    const float* adj_vals = (const float*)d_in[2];
    const int*   up_rows  = (const int*)d_in[3];
    const int*   up_cols  = (const int*)d_in[4];
    const float* up_vals  = (const float*)d_in[5];
    const int*   ip_rows  = (const int*)d_in[6];
    const int*   ip_cols  = (const int*)d_in[7];
    const float* ip_vals  = (const float*)d_in[8];
    const float* Ue       = (const float*)d_in[9];
    const float* Ie       = (const float*)d_in[10];
    const float* Qu       = (const float*)d_in[11];
    const float* Wu       = (const float*)d_in[12];
    const float* bu       = (const float*)d_in[13];
    const float* Qi       = (const float*)d_in[14];
    const float* Wi       = (const float*)d_in[15];
    const float* bi       = (const float*)d_in[16];
    const float* Mu       = (const float*)d_in[17];
    const float* Mi       = (const float*)d_in[18];
    float* out = (float*)d_out;

    static cudaStream_t s1 = 0, s2 = 0;
    static cudaEvent_t evRoot = 0, evScat = 0, evConv = 0, evPair = 0, evHP = 0;
    if (!s1) {
        cudaStreamCreateWithFlags(&s1, cudaStreamNonBlocking);
        cudaStreamCreateWithFlags(&s2, cudaStreamNonBlocking);
        cudaEventCreateWithFlags(&evRoot, cudaEventDisableTiming);
        cudaEventCreateWithFlags(&evScat, cudaEventDisableTiming);
        cudaEventCreateWithFlags(&evConv, cudaEventDisableTiming);
        cudaEventCreateWithFlags(&evPair, cudaEventDisableTiming);
        cudaEventCreateWithFlags(&evHP, cudaEventDisableTiming);
        cudaFuncSetAttribute(k_gemm, cudaFuncAttributeMaxDynamicSharedMemorySize, GSM_TOTAL);
    }

    bf16 *pre0h, *pre0l, *aggh, *aggl, *pairh, *pairl, *embh, *embl;
    bf16 *qth, *qtl, *wth, *wtl, *mth, *mtl;
    float* hbuf;
    cudaGetSymbolAddress((void**)&pre0h, g_pre0h);
    cudaGetSymbolAddress((void**)&pre0l, g_pre0l);
    cudaGetSymbolAddress((void**)&aggh,  g_aggh);
    cudaGetSymbolAddress((void**)&aggl,  g_aggl);
    cudaGetSymbolAddress((void**)&pairh, g_pairh);
    cudaGetSymbolAddress((void**)&pairl, g_pairl);
    cudaGetSymbolAddress((void**)&embh,  g_embh);
    cudaGetSymbolAddress((void**)&embl,  g_embl);
    cudaGetSymbolAddress((void**)&qth,   g_Qth);
    cudaGetSymbolAddress((void**)&qtl,   g_Qtl);
    cudaGetSymbolAddress((void**)&wth,   g_Wth);
    cudaGetSymbolAddress((void**)&wtl,   g_Wtl);
    cudaGetSymbolAddress((void**)&mth,   g_Mth);
    cudaGetSymbolAddress((void**)&mtl,   g_Mtl);
    cudaGetSymbolAddress((void**)&hbuf,  g_h);

    const size_t WSTRIDE = (size_t)2 * DD * DD;  // per-branch W size
    dim3 ggrid(NRB, 2);

    // ---- fork side streams ----
    cudaEventRecord(evRoot, 0);
    cudaStreamWaitEvent(s1, evRoot, 0);
    cudaStreamWaitEvent(s2, evRoot, 0);

    // ---- S1: conversions, then GEMM2a (hpart = pre0 @ W_top) ----
    k_conv_pre0<<<(NT * DD / 4 + 255) / 256, 256, 0, s1>>>(Ue, Ie);
    k_tsplit_all<<<(TS_TOTAL + 255) / 256, 256, 0, s1>>>(Qu, Qi, Mu, Mi, Wu, Wi);
    cudaEventRecord(evConv, s1);
    k_gemm<<<ggrid, 256, GSM_TOTAL, s1>>>(3, 8, 8,
        pre0h, pre0l, pre0h, pre0l,
        wth, wtl, wth + WSTRIDE, wtl + WSTRIDE, 2 * DD,   // W_top: k 0..255
        nullptr, nullptr, nullptr, nullptr, hbuf, nullptr);
    cudaEventRecord(evHP, s1);

    // ---- S0: CSR build ----
    k_zero_cnt<<<(NROWS_ALL + 255) / 256, 256>>>();
    k_hist_all<<<(NNZ_ALL + 255) / 256, 256>>>(adj_rows, up_rows, ip_rows);
    k_scan_blk<<<SCAN_NB, 1024>>>();
    k_scan_top<<<1, 32>>>();
    k_scan_add<<<SCAN_NB, 1024>>>();
    k_scatter_all<<<(NNZ_ALL + 255) / 256, 256>>>(
        adj_rows, adj_cols, adj_vals, up_rows, up_cols, up_vals, ip_rows, ip_cols, ip_vals);
    cudaEventRecord(evScat, 0);

    // ---- S0: agg SpMM ----
    k_spmm<<<(NT + 7) / 8, 256>>>(Ue, Ie, 0, NT);

    // ---- S2: pair SpMM (overlaps agg SpMM tail + GEMMs) ----
    cudaStreamWaitEvent(s2, evScat, 0);
    k_spmm<<<(NU + NI + 7) / 8, 256, 0, s2>>>(Ue, Ie, NT, NROWS_ALL);
    cudaEventRecord(evPair, s2);

    // ---- S0: GEMM 1: emb = tanh(agg @ Q_sel) ----
    cudaStreamWaitEvent(0, evConv, 0);
    k_gemm<<<ggrid, 256, GSM_TOTAL>>>(0, 8, 8,
        aggh, aggl, aggh, aggl,
        qth, qtl, qth + (size_t)DD * DD, qtl + (size_t)DD * DD, DD,
        nullptr, nullptr, embh, embl, nullptr, nullptr);

    // ---- S0: GEMM 2b: h = tanh(hpart + emb @ W_bot + b), row norms ----
    cudaStreamWaitEvent(0, evHP, 0);
    k_gemm<<<ggrid, 256, GSM_TOTAL>>>(1, 8, 8,
        embh, embl, embh, embl,
        wth + DD, wtl + DD, wth + WSTRIDE + DD, wtl + WSTRIDE + DD, 2 * DD,  // W_bot: k 256..511
        bu, bi, nullptr, nullptr, hbuf, hbuf);

    // ---- S0: GEMM 3: out = h/||h|| + tanh(pair @ M_sel) ----
    cudaStreamWaitEvent(0, evPair, 0);
    k_gemm<<<ggrid, 256, GSM_TOTAL>>>(2, 8, 8,
        pairh, pairl, pairh, pairl,
        mth, mtl, mth + (size_t)DD * DD, mtl + (size_t)DD * DD, DD,
        nullptr, nullptr, nullptr, nullptr, out, hbuf);
}

// round 12
// speedup vs baseline: 1.0893x; 1.0893x over previous
#include <cuda_runtime.h>
#include <cuda_bf16.h>
#include <math.h>
#include <stdint.h>

#define NU 40000
#define NI 20000
#define NT 60000
#define DD 256
#define NNZ_ADJ 960000
#define NNZ_UP  640000
#define NNZ_IP  320000
#define NNZ_PAIR (NNZ_UP + NNZ_IP)
#define SCAN_NB ((NT + 1023) / 1024)   /* 59 blocks per 60000-row scan */

#define NRB_U ((NU + 127) / 128)  /* 313 */
#define NRB_I ((NI + 127) / 128)  /* 157 */
#define NRB (NRB_U + NRB_I)       /* 470 */

typedef __nv_bfloat16 bf16;

// ======================= device scratch =====================================
__device__ bf16 g_pre0h[(size_t)NT * DD], g_pre0l[(size_t)NT * DD];
__device__ bf16 g_aggh[(size_t)NT * DD],  g_aggl[(size_t)NT * DD];
__device__ bf16 g_pairh[(size_t)NT * DD], g_pairl[(size_t)NT * DD];
__device__ bf16 g_embh[(size_t)NT * DD],  g_embl[(size_t)NT * DD];
__device__ float g_h[(size_t)NT * DD];
__device__ float g_norm[NT];
// transposed + split weights ([0]=user, [1]=item)
__device__ bf16 g_Qth[2][DD * DD],     g_Qtl[2][DD * DD];
__device__ bf16 g_Wth[2][DD * 2 * DD], g_Wtl[2][DD * 2 * DD];
__device__ bf16 g_Mth[2][DD * DD],     g_Mtl[2][DD * DD];
// CSR build — separate adj / pair chains (60000-row spaces each)
__device__ int   g_cnt_a[NT],  g_cnt_p[NT];
__device__ int   g_rs_a[NT + 1], g_rs_p[NT + 1];
__device__ int   g_cur_a[NT],  g_cur_p[NT];
__device__ int2  g_cpack_a[NNZ_ADJ];
__device__ int2  g_cpack_p[NNZ_PAIR];
__device__ int   g_bsum_a[SCAN_NB], g_boff_a[SCAN_NB + 1];
__device__ int   g_bsum_p[SCAN_NB], g_boff_p[SCAN_NB + 1];

__device__ __forceinline__ void bsplit(float x, bf16& h, bf16& l) {
    h = __float2bfloat16_rn(x);
    l = __float2bfloat16_rn(x - __bfloat162float(h));
}
__device__ __forceinline__ uint32_t smem_u32(const void* p) {
    uint32_t a;
    asm("{ .reg .u64 t; cvta.to.shared.u64 t, %1; cvt.u32.u64 %0, t; }" : "=r"(a) : "l"(p));
    return a;
}

// ======================= CSR build (parameterized) ==========================
__global__ void k_zero_all() {
    int i = blockIdx.x * blockDim.x + threadIdx.x;
    if (i < NT) { g_cnt_a[i] = 0; g_cnt_p[i] = 0; g_norm[i] = 0.f; }
}
__global__ void k_hist(const int* __restrict__ rows, int nnz, int off,
                       int* __restrict__ cnt) {
    int i = blockIdx.x * blockDim.x + threadIdx.x;
    if (i < nnz) atomicAdd(&cnt[rows[i] + off], 1);
}
__global__ __launch_bounds__(1024) void k_scan_blk(const int* __restrict__ cnt,
                                                   int* __restrict__ rs,
                                                   int* __restrict__ bsum) {
    __shared__ int s[1024];
    int i = blockIdx.x * 1024 + threadIdx.x;
    int v = (i < NT) ? cnt[i] : 0;
    s[threadIdx.x] = v;
    __syncthreads();
    int x = v;
    for (int off = 1; off < 1024; off <<= 1) {
        int t = (threadIdx.x >= off) ? s[threadIdx.x - off] : 0;
        __syncthreads();
        x += t;
        s[threadIdx.x] = x;
        __syncthreads();
    }
    if (i < NT) rs[i] = x - v;
    if (threadIdx.x == 1023) bsum[blockIdx.x] = s[1023];
}
__global__ void k_scan_top(const int* __restrict__ bsum, int* __restrict__ boff) {
    if (threadIdx.x == 0) {
        int run = 0;
        for (int b = 0; b < SCAN_NB; b++) { boff[b] = run; run += bsum[b]; }
        boff[SCAN_NB] = run;
    }
}
__global__ void k_scan_add(int* __restrict__ rs, int* __restrict__ cur,
                           const int* __restrict__ boff) {
    int i = blockIdx.x * 1024 + threadIdx.x;
    if (i < NT) {
        int r = rs[i] + boff[i >> 10];
        rs[i] = r;
        cur[i] = r;
    }
    if (i == 0) rs[NT] = boff[SCAN_NB];
}
__global__ void k_scatter(const int* __restrict__ rows, const int* __restrict__ cols,
                          const float* __restrict__ vals, int nnz, int roff,
                          int* __restrict__ cur, int2* __restrict__ cpack) {
    int i = blockIdx.x * blockDim.x + threadIdx.x;
    if (i >= nnz) return;
    int p = atomicAdd(&cur[rows[i] + roff], 1);
    cpack[p] = make_int2(cols[i], __float_as_int(vals[i]));
}

// ======================= CSR SpMM (warp/row, x4 unroll) =====================
// generic over (rs, cpack, colsplit, output)
__device__ __forceinline__ void spmm_row(
    int R, int lane, const int* __restrict__ rs, const int2* __restrict__ cpack,
    const float* __restrict__ X1, const float* __restrict__ X2, int split,
    bf16* __restrict__ oh, bf16* __restrict__ ol)
{
    float4 a0 = make_float4(0.f, 0.f, 0.f, 0.f);
    float4 a1 = a0;
    int beg = rs[R], end = rs[R + 1];
    int e = beg;
    for (; e + 3 < end; e += 4) {
        int2 cv[4];
        const float* xp[4];
        float v[4];
#pragma unroll
        for (int j = 0; j < 4; j++) {
            cv[j] = cpack[e + j];
            v[j] = __int_as_float(cv[j].y);
            xp[j] = (cv[j].x < split) ? (X1 + (size_t)cv[j].x * DD)
                                      : (X2 + (size_t)(cv[j].x - split) * DD);
        }
        float4 p[4], q[4];
#pragma unroll
        for (int j = 0; j < 4; j++) {
            p[j] = *reinterpret_cast<const float4*>(xp[j] + lane * 4);
            q[j] = *reinterpret_cast<const float4*>(xp[j] + 128 + lane * 4);
        }
#pragma unroll
        for (int j = 0; j < 4; j++) {
            a0.x += v[j] * p[j].x; a0.y += v[j] * p[j].y;
            a0.z += v[j] * p[j].z; a0.w += v[j] * p[j].w;
            a1.x += v[j] * q[j].x; a1.y += v[j] * q[j].y;
            a1.z += v[j] * q[j].z; a1.w += v[j] * q[j].w;
        }
    }
    for (; e < end; e++) {
        int2 cv = cpack[e];
        float v = __int_as_float(cv.y);
        const float* x = (cv.x < split) ? (X1 + (size_t)cv.x * DD)
                                        : (X2 + (size_t)(cv.x - split) * DD);
        float4 p0 = *reinterpret_cast<const float4*>(x + lane * 4);
        float4 p1 = *reinterpret_cast<const float4*>(x + 128 + lane * 4);
        a0.x += v * p0.x; a0.y += v * p0.y; a0.z += v * p0.z; a0.w += v * p0.w;
        a1.x += v * p1.x; a1.y += v * p1.y; a1.z += v * p1.z; a1.w += v * p1.w;
    }
    size_t base = (size_t)R * DD + lane * 4;
    bf16 h0, l0, h1, l1, h2, l2, h3, l3;
    bsplit(a0.x, h0, l0); bsplit(a0.y, h1, l1); bsplit(a0.z, h2, l2); bsplit(a0.w, h3, l3);
    oh[base + 0] = h0; oh[base + 1] = h1; oh[base + 2] = h2; oh[base + 3] = h3;
    ol[base + 0] = l0; ol[base + 1] = l1; ol[base + 2] = l2; ol[base + 3] = l3;
    bsplit(a1.x, h0, l0); bsplit(a1.y, h1, l1); bsplit(a1.z, h2, l2); bsplit(a1.w, h3, l3);
    oh[base + 128] = h0; oh[base + 129] = h1; oh[base + 130] = h2; oh[base + 131] = h3;
    ol[base + 128] = l0; ol[base + 129] = l1; ol[base + 130] = l2; ol[base + 131] = l3;
}

__global__ __launch_bounds__(256) void k_spmm_agg(const float* __restrict__ Ue,
                                                  const float* __restrict__ Ie) {
    int R = blockIdx.x * 8 + (threadIdx.x >> 5);
    if (R >= NT) return;
    spmm_row(R, threadIdx.x & 31, g_rs_a, g_cpack_a, Ue, Ie, NU, g_aggh, g_aggl);
}
__global__ __launch_bounds__(256) void k_spmm_pair(const float* __restrict__ Ue,
                                                   const float* __restrict__ Ie) {
    int R = blockIdx.x * 8 + (threadIdx.x >> 5);
    if (R >= NT) return;
    const float* X = (R < NU) ? Ue : Ie;   // up rows gather Ue, ip rows gather Ie
    spmm_row(R, threadIdx.x & 31, g_rs_p, g_cpack_p, X, X, 1 << 30, g_pairh, g_pairl);
}

// ======================= conversions =========================================
__global__ void k_conv_pre0(const float* __restrict__ Ue, const float* __restrict__ Ie) {
    size_t i = (size_t)blockIdx.x * blockDim.x + threadIdx.x;
    if (i >= (size_t)NT * DD / 4) return;
    size_t base = i * 4;
    const float* src = (base < (size_t)NU * DD) ? (Ue + base) : (Ie + base - (size_t)NU * DD);
    float4 v = *reinterpret_cast<const float4*>(src);
    bf16 h, l;
    bsplit(v.x, h, l); g_pre0h[base + 0] = h; g_pre0l[base + 0] = l;
    bsplit(v.y, h, l); g_pre0h[base + 1] = h; g_pre0l[base + 1] = l;
    bsplit(v.z, h, l); g_pre0h[base + 2] = h; g_pre0l[base + 2] = l;
    bsplit(v.w, h, l); g_pre0h[base + 3] = h; g_pre0l[base + 3] = l;
}

#define TS_SMALL (4 * DD * DD)            /* Qu Qi Mu Mi */
#define TS_TOTAL (TS_SMALL + 2 * 2 * DD * DD)
__global__ void k_tsplit_all(
    const float* __restrict__ Qu, const float* __restrict__ Qi,
    const float* __restrict__ Mu, const float* __restrict__ Mi,
    const float* __restrict__ Wu, const float* __restrict__ Wi) {
    int i = blockIdx.x * blockDim.x + threadIdx.x;
    if (i >= TS_TOTAL) return;
    const float* W;
    bf16 *Th, *Tl;
    int K, j;
    if (i < TS_SMALL) {
        int seg = i >> 16; j = i & 65535; K = DD;
        if (seg == 0)      { W = Qu; Th = g_Qth[0]; Tl = g_Qtl[0]; }
        else if (seg == 1) { W = Qi; Th = g_Qth[1]; Tl = g_Qtl[1]; }
        else if (seg == 2) { W = Mu; Th = g_Mth[0]; Tl = g_Mtl[0]; }
        else               { W = Mi; Th = g_Mth[1]; Tl = g_Mtl[1]; }
    } else {
        j = i - TS_SMALL; K = 2 * DD;
        if (j < 2 * DD * DD) { W = Wu; Th = g_Wth[0]; Tl = g_Wtl[0]; }
        else { j -= 2 * DD * DD; W = Wi; Th = g_Wth[1]; Tl = g_Wtl[1]; }
    }
    int k = j >> 8, n = j & 255;
    bf16 h, l;
    bsplit(W[j], h, l);
    Th[(size_t)n * K + k] = h;
    Tl[(size_t)n * K + k] = l;
}

// ======================= legacy-HMMA bf16 GEMM (R10 core, unchanged) ========
__device__ __forceinline__ void mma_bf16(float c[4], const uint32_t a[4],
                                         uint32_t b0, uint32_t b1) {
    asm volatile(
        "mma.sync.aligned.m16n8k16.row.col.f32.bf16.bf16.f32 "
        "{%0,%1,%2,%3}, {%4,%5,%6,%7}, {%8,%9}, {%0,%1,%2,%3};"
        : "+f"(c[0]), "+f"(c[1]), "+f"(c[2]), "+f"(c[3])
        : "r"(a[0]), "r"(a[1]), "r"(a[2]), "r"(a[3]), "r"(b0), "r"(b1));
}

#define SPAD 40
#define SARR (128 * SPAD)
#define STAGE_ELEMS (4 * SARR)
#define STAGE_BYTES (STAGE_ELEMS * 2)     /* 40960 */
#define GSM_TOTAL   (2 * STAGE_BYTES)     /* 81920 -> 2 CTAs/SM */

__device__ __forceinline__ void cpa16(uint32_t dst, const void* src, bool pred) {
    uint32_t sz = pred ? 16u : 0u;
    asm volatile("cp.async.cg.shared.global [%0], [%1], 16, %2;"
                 :: "r"(dst), "l"(src), "r"(sz));
}
#define CP_COMMIT() asm volatile("cp.async.commit_group;" ::: "memory")

__device__ __forceinline__ uint32_t ld32s(const bf16* s, int elem) {
    return *reinterpret_cast<const uint32_t*>(s + elem);
}

// modes: 0 emb=tanh(A@B)->Oh/Ol ; 1 h=tanh(A@B+bias)->Og,+g_norm ; 2 out.
__global__ __launch_bounds__(256, 2) void k_gemm(
    int mode, int nch, int nsplit,
    const bf16* __restrict__ A1h, const bf16* __restrict__ A1l,
    const bf16* __restrict__ A2h, const bf16* __restrict__ A2l,
    const bf16* __restrict__ Bth_u, const bf16* __restrict__ Btl_u,
    const bf16* __restrict__ Bth_i, const bf16* __restrict__ Btl_i, int ldb,
    const float* __restrict__ bias_u, const float* __restrict__ bias_i,
    bf16* __restrict__ Oh, bf16* __restrict__ Ol,
    float* __restrict__ Og, const float* __restrict__ Hin)
{
    extern __shared__ char smem[];
    const uint32_t sbase = smem_u32(smem);

    const int tid = threadIdx.x;
    const int wid = tid >> 5, lane = tid & 31;
    const int wm = wid & 3, wn = wid >> 2;
    const int g = lane >> 2, tg = lane & 3;
    const int b = blockIdx.x;
    const bool user = (b < NRB_U);
    const int row0 = user ? b * 128 : NU + (b - NRB_U) * 128;
    const int row_end = user ? NU : NT;
    const int valid = min(128, row_end - row0);
    const int n0 = blockIdx.y * 128;
    const bf16* __restrict__ Bh = user ? Bth_u : Bth_i;
    const bf16* __restrict__ Bl = user ? Btl_u : Btl_i;
    const float* __restrict__ bias = user ? bias_u : bias_i;

    const int la_r = tid >> 1;
    const int la_kq = (tid & 1) * 2;

    float acc[2][8][4];
#pragma unroll
    for (int mi = 0; mi < 2; mi++)
#pragma unroll
        for (int ni = 0; ni < 8; ni++)
#pragma unroll
            for (int j = 0; j < 4; j++) acc[mi][ni][j] = 0.f;

    auto load_stage = [&](int s, int ch) {
        const bf16* Ah = (ch < nsplit) ? A1h : A2h;
        const bf16* Al = (ch < nsplit) ? A1l : A2l;
        const int ka = ((ch < nsplit) ? ch : ch - nsplit) * 32;
        const int kb = ch * 32;
        const uint32_t st = sbase + s * STAGE_BYTES;
        const uint32_t oAh = st;
        const uint32_t oAl = st + SARR * 2;
        const uint32_t oBh = st + 2 * SARR * 2;
        const uint32_t oBl = st + 3 * SARR * 2;
        bool pa = la_r < valid;
        size_t ga = (size_t)(row0 + (pa ? la_r : 0)) * DD + ka + la_kq * 8;
        size_t gb = (size_t)(n0 + la_r) * ldb + kb + la_kq * 8;
        uint32_t so = (la_r * SPAD + la_kq * 8) * 2;
#pragma unroll
        for (int q = 0; q < 2; q++) {
            uint32_t soq = so + q * 16;
            size_t gaq = ga + q * 8;
            size_t gbq = gb + q * 8;
            cpa16(oAh + soq, Ah + gaq, pa);
            cpa16(oAl + soq, Al + gaq, pa);
            cpa16(oBh + soq, Bh + gbq, true);
            cpa16(oBl + soq, Bl + gbq, true);
        }
        CP_COMMIT();
    };

    load_stage(0, 0);

    for (int ch = 0; ch < nch; ch++) {
        if (ch + 1 < nch) {
            load_stage((ch + 1) & 1, ch + 1);
            asm volatile("cp.async.wait_group 1;" ::: "memory");
        } else {
            asm volatile("cp.async.wait_group 0;" ::: "memory");
        }
        __syncthreads();

        const bf16* st = reinterpret_cast<const bf16*>(smem + (ch & 1) * STAGE_BYTES);
        const bf16* sAh = st;
        const bf16* sAl = st + SARR;
        const bf16* sBh = st + 2 * SARR;
        const bf16* sBl = st + 3 * SARR;

#pragma unroll
        for (int ks = 0; ks < 2; ks++) {
            const int kc = ks * 16 + 2 * tg;
            uint32_t ah[2][4], al[2][4];
#pragma unroll
            for (int mi = 0; mi < 2; mi++) {
                int rb = (wm * 32 + mi * 16 + g) * SPAD;
                ah[mi][0] = ld32s(sAh, rb + kc);
                ah[mi][1] = ld32s(sAh, rb + 8 * SPAD + kc);
                ah[mi][2] = ld32s(sAh, rb + kc + 8);
                ah[mi][3] = ld32s(sAh, rb + 8 * SPAD + kc + 8);
                al[mi][0] = ld32s(sAl, rb + kc);
                al[mi][1] = ld32s(sAl, rb + 8 * SPAD + kc);
                al[mi][2] = ld32s(sAl, rb + kc + 8);
                al[mi][3] = ld32s(sAl, rb + 8 * SPAD + kc + 8);
            }
#pragma unroll
            for (int ni = 0; ni < 8; ni++) {
                int nb = (wn * 64 + ni * 8 + g) * SPAD;
                uint32_t bh0 = ld32s(sBh, nb + kc);
                uint32_t bh1 = ld32s(sBh, nb + kc + 8);
                uint32_t bl0 = ld32s(sBl, nb + kc);
                uint32_t bl1 = ld32s(sBl, nb + kc + 8);
#pragma unroll
                for (int mi = 0; mi < 2; mi++) {
                    mma_bf16(acc[mi][ni], ah[mi], bh0, bh1);
                    mma_bf16(acc[mi][ni], ah[mi], bl0, bl1);
                    mma_bf16(acc[mi][ni], al[mi], bh0, bh1);
                }
            }
        }
        __syncthreads();
    }

    // ---------------- epilogue ----------------
    const int mbase = row0 + wm * 32 + g;
    float scl[2][2];
    if (mode == 2) {
#pragma unroll
        for (int mi = 0; mi < 2; mi++) {
            int r0 = mbase + mi * 16, r1 = r0 + 8;
            scl[mi][0] = (r0 < row_end) ? 1.f / fmaxf(sqrtf(g_norm[r0]), 1e-12f) : 0.f;
            scl[mi][1] = (r1 < row_end) ? 1.f / fmaxf(sqrtf(g_norm[r1]), 1e-12f) : 0.f;
        }
    }
    float ssum[4] = {0.f, 0.f, 0.f, 0.f};

#pragma unroll
    for (int mi = 0; mi < 2; mi++) {
        int r0 = mbase + mi * 16, r1 = r0 + 8;
        bool v0 = (r0 < row_end), v1 = (r1 < row_end);
#pragma unroll
        for (int ni = 0; ni < 8; ni++) {
            int col = n0 + wn * 64 + ni * 8 + 2 * tg;
            float* a = acc[mi][ni];
            if (mode == 0) {
                if (v0) {
                    float t0 = tanhf(a[0]), t1 = tanhf(a[1]);
                    bf16 h0, l0, h1, l1;
                    bsplit(t0, h0, l0); bsplit(t1, h1, l1);
                    size_t idx = (size_t)r0 * DD + col;
                    *reinterpret_cast<__nv_bfloat162*>(Oh + idx) = __nv_bfloat162(h0, h1);
                    *reinterpret_cast<__nv_bfloat162*>(Ol + idx) = __nv_bfloat162(l0, l1);
                }
                if (v1) {
                    float t2 = tanhf(a[2]), t3 = tanhf(a[3]);
                    bf16 h2, l2, h3, l3;
                    bsplit(t2, h2, l2); bsplit(t3, h3, l3);
                    size_t idx = (size_t)r1 * DD + col;
                    *reinterpret_cast<__nv_bfloat162*>(Oh + idx) = __nv_bfloat162(h2, h3);
                    *reinterpret_cast<__nv_bfloat162*>(Ol + idx) = __nv_bfloat162(l2, l3);
                }
            } else if (mode == 1) {
                float b0v = bias[col], b1v = bias[col + 1];
                if (v0) {
                    float t0 = tanhf(a[0] + b0v), t1 = tanhf(a[1] + b1v);
                    size_t idx = (size_t)r0 * DD + col;
                    Og[idx] = t0; Og[idx + 1] = t1;
                    ssum[mi * 2] += t0 * t0 + t1 * t1;
                }
                if (v1) {
                    float t2 = tanhf(a[2] + b0v), t3 = tanhf(a[3] + b1v);
                    size_t idx = (size_t)r1 * DD + col;
                    Og[idx] = t2; Og[idx + 1] = t3;
                    ssum[mi * 2 + 1] += t2 * t2 + t3 * t3;
                }
            } else {
                if (v0) {
                    size_t idx = (size_t)r0 * DD + col;
                    Og[idx]     = Hin[idx]     * scl[mi][0] + tanhf(a[0]);
                    Og[idx + 1] = Hin[idx + 1] * scl[mi][0] + tanhf(a[1]);
                }
                if (v1) {
                    size_t idx = (size_t)r1 * DD + col;
                    Og[idx]     = Hin[idx]     * scl[mi][1] + tanhf(a[2]);
                    Og[idx + 1] = Hin[idx + 1] * scl[mi][1] + tanhf(a[3]);
                }
            }
        }
    }
    if (mode == 1) {
#pragma unroll
        for (int j = 0; j < 4; j++) {
            ssum[j] += __shfl_xor_sync(0xFFFFFFFF, ssum[j], 1);
            ssum[j] += __shfl_xor_sync(0xFFFFFFFF, ssum[j], 2);
        }
        if (tg == 0) {
#pragma unroll
            for (int mi = 0; mi < 2; mi++) {
                int r0 = mbase + mi * 16, r1 = r0 + 8;
                if (r0 < row_end) atomicAdd(&g_norm[r0], ssum[mi * 2]);
                if (r1 < row_end) atomicAdd(&g_norm[r1], ssum[mi * 2 + 1]);
            }
        }
    }
}

// ======================= host ================================================
extern "C" void kernel_launch(void* const* d_in, const int* in_sizes, int n_in,
                              void* d_out, int out_size) {
    const int*   adj_rows = (const int*)d_in[0];
    const int*   adj_cols = (const int*)d_in[1];
    const float* adj_vals = (const float*)d_in[2];
    const int*   up_rows  = (const int*)d_in[3];
    const int*   up_cols  = (const int*)d_in[4];
    const float* up_vals  = (const float*)d_in[5];
    const int*   ip_rows  = (const int*)d_in[6];
    const int*   ip_cols  = (const int*)d_in[7];
    const float* ip_vals  = (const float*)d_in[8];
    const float* Ue       = (const float*)d_in[9];
    const float* Ie       = (const float*)d_in[10];
    const float* Qu       = (const float*)d_in[11];
    const float* Wu       = (const float*)d_in[12];
    const float* bu       = (const float*)d_in[13];
    const float* Qi       = (const float*)d_in[14];
    const float* Wi       = (const float*)d_in[15];
    const float* bi       = (const float*)d_in[16];
    const float* Mu       = (const float*)d_in[17];
    const float* Mi       = (const float*)d_in[18];
    float* out = (float*)d_out;

    static cudaStream_t s1 = 0, s2 = 0;
    static cudaEvent_t evRoot = 0, evZero = 0, evConv = 0, evPair = 0;
    if (!s1) {
        cudaStreamCreateWithFlags(&s1, cudaStreamNonBlocking);
        cudaStreamCreateWithFlags(&s2, cudaStreamNonBlocking);
        cudaEventCreateWithFlags(&evRoot, cudaEventDisableTiming);
        cudaEventCreateWithFlags(&evZero, cudaEventDisableTiming);
        cudaEventCreateWithFlags(&evConv, cudaEventDisableTiming);
        cudaEventCreateWithFlags(&evPair, cudaEventDisableTiming);
        cudaFuncSetAttribute(k_gemm, cudaFuncAttributeMaxDynamicSharedMemorySize, GSM_TOTAL);
    }

    bf16 *pre0h, *pre0l, *aggh, *aggl, *pairh, *pairl, *embh, *embl;
    bf16 *qth, *qtl, *wth, *wtl, *mth, *mtl;
    float* hbuf;
    int *cnt_a, *rs_a, *cur_a, *bsum_a, *boff_a;
    int *cnt_p, *rs_p, *cur_p, *bsum_p, *boff_p;
    int2 *cpack_a, *cpack_p;
    cudaGetSymbolAddress((void**)&pre0h, g_pre0h);
    cudaGetSymbolAddress((void**)&pre0l, g_pre0l);
    cudaGetSymbolAddress((void**)&aggh,  g_aggh);
    cudaGetSymbolAddress((void**)&aggl,  g_aggl);
    cudaGetSymbolAddress((void**)&pairh, g_pairh);
    cudaGetSymbolAddress((void**)&pairl, g_pairl);
    cudaGetSymbolAddress((void**)&embh,  g_embh);
    cudaGetSymbolAddress((void**)&embl,  g_embl);
    cudaGetSymbolAddress((void**)&qth,   g_Qth);
    cudaGetSymbolAddress((void**)&qtl,   g_Qtl);
    cudaGetSymbolAddress((void**)&wth,   g_Wth);
    cudaGetSymbolAddress((void**)&wtl,   g_Wtl);
    cudaGetSymbolAddress((void**)&mth,   g_Mth);
    cudaGetSymbolAddress((void**)&mtl,   g_Mtl);
    cudaGetSymbolAddress((void**)&hbuf,  g_h);
    cudaGetSymbolAddress((void**)&cnt_a,  g_cnt_a);
    cudaGetSymbolAddress((void**)&rs_a,   g_rs_a);
    cudaGetSymbolAddress((void**)&cur_a,  g_cur_a);
    cudaGetSymbolAddress((void**)&bsum_a, g_bsum_a);
    cudaGetSymbolAddress((void**)&boff_a, g_boff_a);
    cudaGetSymbolAddress((void**)&cnt_p,  g_cnt_p);
    cudaGetSymbolAddress((void**)&rs_p,   g_rs_p);
    cudaGetSymbolAddress((void**)&cur_p,  g_cur_p);
    cudaGetSymbolAddress((void**)&bsum_p, g_bsum_p);
    cudaGetSymbolAddress((void**)&boff_p, g_boff_p);
    cudaGetSymbolAddress((void**)&cpack_a, g_cpack_a);
    cudaGetSymbolAddress((void**)&cpack_p, g_cpack_p);

    // ---- fork side streams ----
    cudaEventRecord(evRoot, 0);
    cudaStreamWaitEvent(s1, evRoot, 0);
    cudaStreamWaitEvent(s2, evRoot, 0);

    // ---- S1: conversions (independent) ----
    k_conv_pre0<<<(NT * DD / 4 + 255) / 256, 256, 0, s1>>>(Ue, Ie);
    k_tsplit_all<<<(TS_TOTAL + 255) / 256, 256, 0, s1>>>(Qu, Qi, Mu, Mi, Wu, Wi);
    cudaEventRecord(evConv, s1);

    // ---- S0: zero, then adj-only CSR chain -> agg SpMM ----
    k_zero_all<<<(NT + 255) / 256, 256>>>();
    cudaEventRecord(evZero, 0);
    k_hist<<<(NNZ_ADJ + 255) / 256, 256>>>(adj_rows, NNZ_ADJ, 0, cnt_a);
    k_scan_blk<<<SCAN_NB, 1024>>>(cnt_a, rs_a, bsum_a);
    k_scan_top<<<1, 32>>>(bsum_a, boff_a);
    k_scan_add<<<SCAN_NB, 1024>>>(rs_a, cur_a, boff_a);
    k_scatter<<<(NNZ_ADJ + 255) / 256, 256>>>(adj_rows, adj_cols, adj_vals,
                                              NNZ_ADJ, 0, cur_a, cpack_a);
    k_spmm_agg<<<(NT + 7) / 8, 256>>>(Ue, Ie);

    // ---- S2: pair-only CSR chain -> pair SpMM (fully off critical path) ----
    cudaStreamWaitEvent(s2, evZero, 0);
    k_hist<<<(NNZ_UP + 255) / 256, 256, 0, s2>>>(up_rows, NNZ_UP, 0, cnt_p);
    k_hist<<<(NNZ_IP + 255) / 256, 256, 0, s2>>>(ip_rows, NNZ_IP, NU, cnt_p);
    k_scan_blk<<<SCAN_NB, 1024, 0, s2>>>(cnt_p, rs_p, bsum_p);
    k_scan_top<<<1, 32, 0, s2>>>(bsum_p, boff_p);
    k_scan_add<<<SCAN_NB, 1024, 0, s2>>>(rs_p, cur_p, boff_p);
    k_scatter<<<(NNZ_UP + 255) / 256, 256, 0, s2>>>(up_rows, up_cols, up_vals,
                                                    NNZ_UP, 0, cur_p, cpack_p);
    k_scatter<<<(NNZ_IP + 255) / 256, 256, 0, s2>>>(ip_rows, ip_cols, ip_vals,
                                                    NNZ_IP, NU, cur_p, cpack_p);
    k_spmm_pair<<<(NT + 7) / 8, 256, 0, s2>>>(Ue, Ie);
    cudaEventRecord(evPair, s2);

    dim3 ggrid(NRB, 2);

    // ---- S0: GEMM 1: emb = tanh(agg @ Q_sel) ----
    cudaStreamWaitEvent(0, evConv, 0);
    k_gemm<<<ggrid, 256, GSM_TOTAL>>>(0, 8, 8,
        aggh, aggl, aggh, aggl,
        qth, qtl, qth + (size_t)DD * DD, qtl + (size_t)DD * DD, DD,
        nullptr, nullptr, embh, embl, nullptr, nullptr);

    // ---- S0: GEMM 2: h = tanh([pre0, emb] @ W_sel + b_sel), row norms ----
    k_gemm<<<ggrid, 256, GSM_TOTAL>>>(1, 16, 8,
        pre0h, pre0l, embh, embl,
        wth, wtl, wth + (size_t)2 * DD * DD, wtl + (size_t)2 * DD * DD, 2 * DD,
        bu, bi, nullptr, nullptr, hbuf, nullptr);

    // ---- S0: GEMM 3: out = h/||h|| + tanh(pair @ M_sel) ----
    cudaStreamWaitEvent(0, evPair, 0);
    k_gemm<<<ggrid, 256, GSM_TOTAL>>>(2, 8, 8,
        pairh, pairl, pairh, pairl,
        mth, mtl, mth + (size_t)DD * DD, mtl + (size_t)DD * DD, DD,
        nullptr, nullptr, nullptr, nullptr, out, hbuf);
}